// round 6
// baseline (speedup 1.0000x reference)
#include <cuda_runtime.h>
#include <cstdint>

#define B_       4
#define COUT     256
#define HW       128
#define WD       512
#define LRELU_S  0.2f

// ---------------- device scratch (zero-initialized; borders stay zero) ----
__device__ float g_xum[B_ * 130 * 130 * 512];   // padded NHWC, tf32, premod s1
__device__ float g_h1m[B_ * 130 * 130 * 256];   // padded NHWC, tf32, premod s2
__device__ float g_wpk1[9 * 256 * 512];         // [tap][co][ci] tf32
__device__ float g_wpk2[9 * 256 * 256];
__device__ float g_wm3[B_ * 3 * 256];           // rgb weights premod s3
__device__ float g_s1[B_ * 512];
__device__ float g_s2[B_ * 256];
__device__ float g_s3[B_ * 256];
__device__ float g_d1[B_ * 256];
__device__ float g_d2[B_ * 256];
__device__ float g_wsq1[256 * 512];
__device__ float g_wsq2[256 * 256];

// ---------------- helpers -------------------------------------------------
__device__ __forceinline__ uint32_t smem_u32(const void* p) {
    uint32_t a;
    asm("{ .reg .u64 t; cvta.to.shared.u64 t, %1; cvt.u32.u64 %0, t; }" : "=r"(a) : "l"(p));
    return a;
}
__device__ __forceinline__ float to_tf32(float x) {
    float r; asm("cvt.rna.tf32.f32 %0, %1;" : "=f"(r) : "f"(x)); return r;
}
__device__ __forceinline__ void cp16(uint32_t dst, const void* src) {
    asm volatile("cp.async.ca.shared.global [%0], [%1], 16;" :: "r"(dst), "l"(src));
}
__device__ __forceinline__ void mma_tf32(float* c, const uint32_t* a, const uint32_t* b) {
    asm volatile(
        "mma.sync.aligned.m16n8k8.row.col.f32.tf32.tf32.f32 "
        "{%0,%1,%2,%3}, {%4,%5,%6,%7}, {%8,%9}, {%0,%1,%2,%3};"
        : "+f"(c[0]), "+f"(c[1]), "+f"(c[2]), "+f"(c[3])
        : "r"(a[0]), "r"(a[1]), "r"(a[2]), "r"(a[3]), "r"(b[0]), "r"(b[1]));
}

// ---------------- merged prep kernels ------------------------------------
// L0: all three styles, warp per output
__global__ void style_all(const float* __restrict__ w,
                          const float* __restrict__ a1w, const float* __restrict__ a1b,
                          const float* __restrict__ a2w, const float* __restrict__ a2b,
                          const float* __restrict__ a3w, const float* __restrict__ a3b,
                          float* __restrict__ s1, float* __restrict__ s2,
                          float* __restrict__ s3) {
    int gw = (blockIdx.x * blockDim.x + threadIdx.x) >> 5;
    int lane = threadIdx.x & 31;
    const float* aw; const float* ab; float* s; int C; int g;
    if (gw < 2048)      { aw = a1w; ab = a1b; s = s1; C = 512; g = gw; }
    else if (gw < 3072) { aw = a2w; ab = a2b; s = s2; C = 256; g = gw - 2048; }
    else                { aw = a3w; ab = a3b; s = s3; C = 256; g = gw - 3072; }
    int b = g / C, c = g - b * C;
    const float* wr = w + b * WD;
    const float* ar = aw + (size_t)c * WD;
    float acc = 0.f;
#pragma unroll
    for (int k = 0; k < WD / 32; k++) acc += wr[lane + 32 * k] * ar[lane + 32 * k];
#pragma unroll
    for (int o = 16; o; o >>= 1) acc += __shfl_xor_sync(~0u, acc, o);
    if (!lane) s[g] = acc + ab[c];
}

// L1: wsq for both conv weights
__global__ void wsq_all(const float* __restrict__ w1, const float* __restrict__ w2,
                        float* __restrict__ wsq1, float* __restrict__ wsq2) {
    int i = blockIdx.x * blockDim.x + threadIdx.x;
    const float* w; float* o; int j;
    if (i < 256 * 512) { w = w1; o = wsq1; j = i; }
    else if (i < 256 * 512 + 256 * 256) { w = w2; o = wsq2; j = i - 256 * 512; }
    else return;
    float a = 0.f;
#pragma unroll
    for (int k = 0; k < 9; k++) { float v = w[(size_t)j * 9 + k]; a += v * v; }
    o[j] = a;
}

// L2: demod for both convs, warp per output
__global__ void demod_all(const float* __restrict__ s1, const float* __restrict__ wsq1,
                          const float* __restrict__ s2, const float* __restrict__ wsq2,
                          float* __restrict__ d1, float* __restrict__ d2) {
    int gw = (blockIdx.x * blockDim.x + threadIdx.x) >> 5;
    int lane = threadIdx.x & 31;
    const float* s; const float* wsq; float* d; int Cin; int g;
    if (gw < 1024) { s = s1; wsq = wsq1; d = d1; Cin = 512; g = gw; }
    else           { s = s2; wsq = wsq2; d = d2; Cin = 256; g = gw - 1024; }
    int b = g >> 8, co = g & 255;
    const float* sr = s + b * Cin;
    const float* wr = wsq + (size_t)co * Cin;
    float acc = 0.f;
    for (int c = lane; c < Cin; c += 32) { float sv = sr[c]; acc += sv * sv * wr[c]; }
#pragma unroll
    for (int o = 16; o; o >>= 1) acc += __shfl_xor_sync(~0u, acc, o);
    if (!lane) d[g] = rsqrtf(acc + 1e-8f);
}

// L3: prepack both conv weights [tap][co][ci] tf32 + premodulated rgb weights
__global__ void pack_all(const float* __restrict__ w1, const float* __restrict__ w2,
                         const float* __restrict__ w3, const float* __restrict__ s3,
                         float* __restrict__ wpk1, float* __restrict__ wpk2,
                         float* __restrict__ wm3) {
    int i = blockIdx.x * 256 + threadIdx.x;
    if (i < 9 * 256 * 512) {
        int ci = i & 511; int t = i >> 9; int co = t & 255; int tap = t >> 8;
        wpk1[i] = to_tf32(w1[((size_t)co * 512 + ci) * 9 + tap]);
    } else if (i < 9 * 256 * 512 + 9 * 256 * 256) {
        int j = i - 9 * 256 * 512;
        int ci = j & 255; int t = j >> 8; int co = t & 255; int tap = t >> 8;
        wpk2[j] = to_tf32(w2[((size_t)co * 256 + ci) * 9 + tap]);
    } else {
        int j = i - 9 * 256 * 512 - 9 * 256 * 256;
        if (j < B_ * 3 * 256) {
            int c = j & 255; int t = j >> 8; int r = t % 3; int b = t / 3;
            wm3[j] = w3[r * 256 + c] * s3[b * 256 + c];
        }
    }
}

// L4: bilinear 2x upsample (half-pixel, edge clamp) * s1 -> padded NHWC tf32
__global__ void __launch_bounds__(256)
upmod_kernel(const float* __restrict__ x, const float* __restrict__ s1,
             float* __restrict__ out) {
    __shared__ float st[2][32][21];
    const int tid = threadIdx.x;
    const int x0 = blockIdx.x * 32;
    const int y  = blockIdx.y;
    const int b  = blockIdx.z >> 4;
    const int ci0 = (blockIdx.z & 15) * 32;
    const int y0i = (y - 1) >> 1;
    const int yrow[2] = { max(y0i, 0), min(y0i + 1, 63) };
    const float fy = (y & 1) ? 0.25f : 0.75f;
    const int xs0 = (x0 >> 1) - 1;
    for (int t = tid; t < 32 * 2 * 18; t += 256) {
        int xi = t % 18;
        int rr = (t / 18) & 1;
        int ci = t / 36;
        int xs = min(max(xs0 + xi, 0), 63);
        st[rr][ci][xi] = x[(((size_t)b * 512 + ci0 + ci) * 64 + yrow[rr]) * 64 + xs];
    }
    __syncthreads();
    const int ci = tid & 31;
    const int jg = tid >> 5;
    const float sv = s1[b * 512 + ci0 + ci];
    float* ob = out + (((size_t)b * 130 + 1 + y) * 130 + 1 + x0) * 512 + ci0 + ci;
#pragma unroll
    for (int q = 0; q < 4; q++) {
        int j = jg * 4 + q;
        int xi = (j + 1) >> 1;
        float fx = (j & 1) ? 0.25f : 0.75f;
        float v0 = st[0][ci][xi] * (1.f - fx) + st[0][ci][xi + 1] * fx;
        float v1 = st[1][ci][xi] * (1.f - fx) + st[1][ci][xi + 1] * fx;
        ob[(size_t)j * 512] = to_tf32((v0 * (1.f - fy) + v1 * fy) * sv);
    }
}

// ---------------- tf32 mma.sync implicit-GEMM 3x3 conv --------------------
// CTA: M = 256 pixels (2 rows of 128, blockIdx.x), N = 128 co (blockIdx.y), b = z.
// 8 warps = 4(M) x 2(N), warp tile 64x64 via m16n8k8.
// 3-stage cp.async pipeline, ONE __syncthreads per k-chunk:
//   wait_group(1) -> barrier -> issue(i+2) -> compute(i)
// smem: act [3][256][36], wgt [3][128][36] (stride 36 -> conflict-free frags).
template<int CIN, bool NHWC_OUT>
__global__ void __launch_bounds__(256, 1)
conv3x3_mma(const float* __restrict__ in, const float* __restrict__ wpk,
            const float* __restrict__ bias, const float* __restrict__ demod,
            const float* __restrict__ postscale, float* __restrict__ out) {
    constexpr int CPT = CIN / 32;
    constexpr int NCH = 9 * CPT;
    constexpr int PADIN = 130;
    constexpr int ACT_F = 256 * 36;
    constexpr int W_F   = 128 * 36;
    extern __shared__ float smf[];
    const uint32_t smb = smem_u32(smf);

    const int tid = threadIdx.x;
    const int wid = tid >> 5, lane = tid & 31;
    const int gq = lane >> 2, tg = lane & 3;
    const int wm = wid >> 1;            // 0..3 (pixel quarter)
    const int wn = wid & 1;             // 0..1 (co half)
    const int y0 = blockIdx.x * 2;
    const int co0 = blockIdx.y * 128;
    const int b  = blockIdx.z;

    float acc[4][8][4];
#pragma unroll
    for (int mi = 0; mi < 4; mi++)
#pragma unroll
        for (int ni = 0; ni < 8; ni++)
#pragma unroll
            for (int k = 0; k < 4; k++) acc[mi][ni][k] = 0.f;

    auto issue = [&](int i) {
        const int s = i % 3;
        const int tap = i / CPT;
        const int cc = (i - tap * CPT) * 32;
        const int dy = tap / 3 - 1, dx = tap % 3 - 1;
        const float* abase = in + ((((size_t)b * PADIN + (y0 + dy + 1)) * PADIN + (1 + dx)) * CIN + cc);
        const uint32_t adst = smb + s * (ACT_F * 4);
#pragma unroll
        for (int r = 0; r < 8; r++) {
            int t = tid + r * 256;
            int row = t >> 3, j = t & 7;
            const float* src = abase + (size_t)(row >> 7) * (PADIN * CIN) + (size_t)(row & 127) * CIN + j * 4;
            cp16(adst + (uint32_t)(row * 36 + j * 4) * 4, src);
        }
        const float* wbase = wpk + ((size_t)(tap * 256 + co0)) * CIN + cc;
        const uint32_t wdst = smb + (3 * ACT_F + s * W_F) * 4;
#pragma unroll
        for (int r = 0; r < 4; r++) {
            int t = tid + r * 256;
            int row = t >> 3, j = t & 7;
            cp16(wdst + (uint32_t)(row * 36 + j * 4) * 4, wbase + (size_t)row * CIN + j * 4);
        }
        asm volatile("cp.async.commit_group;" ::: "memory");
    };

    issue(0);
    issue(1);
    for (int i = 0; i < NCH; i++) {
        const int s = i % 3;
        if (i + 1 < NCH) asm volatile("cp.async.wait_group 1;" ::: "memory");
        else             asm volatile("cp.async.wait_group 0;" ::: "memory");
        __syncthreads();
        if (i + 2 < NCH) issue(i + 2);

        const float* As_ = smf + s * ACT_F;
        const float* Ws_ = smf + 3 * ACT_F + s * W_F;
#pragma unroll
        for (int k8 = 0; k8 < 4; k8++) {
            const int k0 = k8 * 8;
            uint32_t af[4][4];
#pragma unroll
            for (int mi = 0; mi < 4; mi++) {
                const float* ap = As_ + (wm * 64 + mi * 16) * 36 + k0;
                af[mi][0] = __float_as_uint(ap[gq * 36 + tg]);
                af[mi][1] = __float_as_uint(ap[(gq + 8) * 36 + tg]);
                af[mi][2] = __float_as_uint(ap[gq * 36 + tg + 4]);
                af[mi][3] = __float_as_uint(ap[(gq + 8) * 36 + tg + 4]);
            }
#pragma unroll
            for (int ni = 0; ni < 8; ni++) {
                const float* bp = Ws_ + (wn * 64 + ni * 8 + gq) * 36 + k0;
                uint32_t bf[2];
                bf[0] = __float_as_uint(bp[tg]);
                bf[1] = __float_as_uint(bp[tg + 4]);
#pragma unroll
                for (int mi = 0; mi < 4; mi++) mma_tf32(acc[mi][ni], af[mi], bf);
            }
        }
    }

    // epilogue
#pragma unroll
    for (int ni = 0; ni < 8; ni++) {
        const int co = co0 + wn * 64 + ni * 8 + 2 * tg;
        const float dm0 = demod[b * 256 + co],  dm1 = demod[b * 256 + co + 1];
        const float bi0 = bias[co],             bi1 = bias[co + 1];
        float ps0 = 1.f, ps1 = 1.f;
        if (NHWC_OUT) { ps0 = postscale[b * 256 + co]; ps1 = postscale[b * 256 + co + 1]; }
#pragma unroll
        for (int mi = 0; mi < 4; mi++) {
#pragma unroll
            for (int h = 0; h < 2; h++) {
                const int m = wm * 64 + mi * 16 + gq + h * 8;
                const int y = y0 + (m >> 7), xx = m & 127;
                float v0 = acc[mi][ni][2 * h + 0] * dm0 + bi0;
                float v1 = acc[mi][ni][2 * h + 1] * dm1 + bi1;
                v0 = v0 > 0.f ? v0 : LRELU_S * v0;
                v1 = v1 > 0.f ? v1 : LRELU_S * v1;
                if (NHWC_OUT) {
                    // padded NHWC tf32, premod next-layer style
                    float2 o = { to_tf32(v0 * ps0), to_tf32(v1 * ps1) };
                    *(float2*)(out + (((size_t)b * 130 + 1 + y) * 130 + 1 + xx) * 256 + co) = o;
                } else {
                    // NCHW fp32 (final h) — 8 consecutive lanes give 32B sectors
                    out[(((size_t)b * 256 + co)     * 128 + y) * 128 + xx] = v0;
                    out[(((size_t)b * 256 + co + 1) * 128 + y) * 128 + xx] = v1;
                }
            }
        }
    }
}

// rgb from NCHW h: pixel per thread, coalesced per-ci loads
__global__ void __launch_bounds__(256)
rgb_nchw(const float* __restrict__ h, const float* __restrict__ wm3,
         const float* __restrict__ b3, float* __restrict__ rgb) {
    const int idx = blockIdx.x * 256 + threadIdx.x;
    const int b = idx >> 14, pix = idx & 16383;
    const float* hp = h + (size_t)b * 256 * 16384 + pix;
    const float* wp = wm3 + b * 768;
    float a0 = 0.f, a1 = 0.f, a2 = 0.f;
#pragma unroll 4
    for (int c = 0; c < 256; c++) {
        float hv = hp[(size_t)c * 16384];
        a0 += wp[c] * hv;
        a1 += wp[256 + c] * hv;
        a2 += wp[512 + c] * hv;
    }
    float r0 = a0 + b3[0]; r0 = r0 > 0.f ? r0 : LRELU_S * r0;
    float r1 = a1 + b3[1]; r1 = r1 > 0.f ? r1 : LRELU_S * r1;
    float r2 = a2 + b3[2]; r2 = r2 > 0.f ? r2 : LRELU_S * r2;
    rgb[((size_t)b * 3 + 0) * 16384 + pix] = r0;
    rgb[((size_t)b * 3 + 1) * 16384 + pix] = r1;
    rgb[((size_t)b * 3 + 2) * 16384 + pix] = r2;
}

extern "C" void kernel_launch(void* const* d_in, const int* in_sizes, int n_in,
                              void* d_out, int out_size) {
    const float* x   = (const float*)d_in[0];
    const float* w   = (const float*)d_in[1];
    const float* w1  = (const float*)d_in[2];
    const float* b1  = (const float*)d_in[3];
    const float* a1w = (const float*)d_in[4];
    const float* a1b = (const float*)d_in[5];
    const float* w2  = (const float*)d_in[6];
    const float* b2  = (const float*)d_in[7];
    const float* a2w = (const float*)d_in[8];
    const float* a2b = (const float*)d_in[9];
    const float* w3  = (const float*)d_in[10];
    const float* b3  = (const float*)d_in[11];
    const float* a3w = (const float*)d_in[12];
    const float* a3b = (const float*)d_in[13];

    float* out_h   = (float*)d_out;
    float* out_rgb = out_h + (size_t)B_ * COUT * HW * HW;

    float *xum, *h1m, *s1, *s2, *s3, *d1, *d2, *wsq1, *wsq2, *wpk1, *wpk2, *wm3;
    cudaGetSymbolAddress((void**)&xum,  g_xum);
    cudaGetSymbolAddress((void**)&h1m,  g_h1m);
    cudaGetSymbolAddress((void**)&s1,   g_s1);
    cudaGetSymbolAddress((void**)&s2,   g_s2);
    cudaGetSymbolAddress((void**)&s3,   g_s3);
    cudaGetSymbolAddress((void**)&d1,   g_d1);
    cudaGetSymbolAddress((void**)&d2,   g_d2);
    cudaGetSymbolAddress((void**)&wsq1, g_wsq1);
    cudaGetSymbolAddress((void**)&wsq2, g_wsq2);
    cudaGetSymbolAddress((void**)&wpk1, g_wpk1);
    cudaGetSymbolAddress((void**)&wpk2, g_wpk2);
    cudaGetSymbolAddress((void**)&wm3,  g_wm3);

    const int SMEM_DYN = (3 * 256 * 36 + 3 * 128 * 36) * 4;   // 165888 B
    cudaFuncSetAttribute(conv3x3_mma<512, true>,
                         cudaFuncAttributeMaxDynamicSharedMemorySize, SMEM_DYN);
    cudaFuncSetAttribute(conv3x3_mma<256, false>,
                         cudaFuncAttributeMaxDynamicSharedMemorySize, SMEM_DYN);

    // L0..L3: merged prep (4 launches)
    style_all<<<512, 256>>>(w, a1w, a1b, a2w, a2b, a3w, a3b, s1, s2, s3);
    wsq_all<<<(256 * 512 + 256 * 256 + 255) / 256, 256>>>(w1, w2, wsq1, wsq2);
    demod_all<<<256, 256>>>(s1, wsq1, s2, wsq2, d1, d2);
    pack_all<<<(9 * 256 * 512 + 9 * 256 * 256 + B_ * 3 * 256 + 255) / 256, 256>>>(
        w1, w2, w3, s3, wpk1, wpk2, wm3);

    // L4: upsample + modulate -> padded NHWC tf32
    upmod_kernel<<<dim3(4, 128, 64), 256>>>(x, s1, xum);

    // L5 (ncu -s 5 captures this): conv1 512->256, epi *d1+b1, lrelu, *s2 -> h1m
    conv3x3_mma<512, true><<<dim3(64, 2, 4), 256, SMEM_DYN>>>(xum, wpk1, b1, d1, s2, h1m);
    // L6: conv2 256->256, epi *d2+b2, lrelu -> out_h (NCHW fp32, direct)
    conv3x3_mma<256, false><<<dim3(64, 2, 4), 256, SMEM_DYN>>>(h1m, wpk2, b2, d2,
                                                               (const float*)nullptr, out_h);
    // L7: rgb from NCHW h
    rgb_nchw<<<(B_ * HW * HW) / 256, 256>>>(out_h, wm3, b3, out_rgb);
}

// round 7
// speedup vs baseline: 1.4252x; 1.4252x over previous
#include <cuda_runtime.h>
#include <cuda_fp16.h>
#include <cstdint>

#define B_       4
#define COUT     256
#define HW       128
#define WD       512
#define LRELU_S  0.2f

// ---------------- device scratch (zero-initialized; borders stay zero) ----
__device__ __half g_xum[B_ * 130 * 130 * 512];  // padded NHWC fp16, premod s1
__device__ __half g_h1m[B_ * 130 * 130 * 256];  // padded NHWC fp16, premod s2
__device__ __half g_wpk1[9 * 256 * 512];        // [tap][co][ci] fp16
__device__ __half g_wpk2[9 * 256 * 256];
__device__ float g_wm3[B_ * 3 * 256];           // rgb weights premod s3
__device__ float g_s1[B_ * 512];
__device__ float g_s2[B_ * 256];
__device__ float g_s3[B_ * 256];
__device__ float g_d1[B_ * 256];
__device__ float g_d2[B_ * 256];
__device__ float g_wsq1[256 * 512];
__device__ float g_wsq2[256 * 256];

// ---------------- helpers -------------------------------------------------
__device__ __forceinline__ uint32_t smem_u32(const void* p) {
    uint32_t a;
    asm("{ .reg .u64 t; cvta.to.shared.u64 t, %1; cvt.u32.u64 %0, t; }" : "=r"(a) : "l"(p));
    return a;
}
__device__ __forceinline__ void cp16(uint32_t dst, const void* src) {
    asm volatile("cp.async.ca.shared.global [%0], [%1], 16;" :: "r"(dst), "l"(src));
}
// fp16 tensor-core mma, fp32 accumulate
__device__ __forceinline__ void mma_f16(float* c, const uint32_t* a, const uint32_t* b) {
    asm volatile(
        "mma.sync.aligned.m16n8k16.row.col.f32.f16.f16.f32 "
        "{%0,%1,%2,%3}, {%4,%5,%6,%7}, {%8,%9}, {%0,%1,%2,%3};"
        : "+f"(c[0]), "+f"(c[1]), "+f"(c[2]), "+f"(c[3])
        : "r"(a[0]), "r"(a[1]), "r"(a[2]), "r"(a[3]), "r"(b[0]), "r"(b[1]));
}

// ---------------- merged prep kernels ------------------------------------
__global__ void style_all(const float* __restrict__ w,
                          const float* __restrict__ a1w, const float* __restrict__ a1b,
                          const float* __restrict__ a2w, const float* __restrict__ a2b,
                          const float* __restrict__ a3w, const float* __restrict__ a3b,
                          float* __restrict__ s1, float* __restrict__ s2,
                          float* __restrict__ s3) {
    int gw = (blockIdx.x * blockDim.x + threadIdx.x) >> 5;
    int lane = threadIdx.x & 31;
    const float* aw; const float* ab; float* s; int C; int g;
    if (gw < 2048)      { aw = a1w; ab = a1b; s = s1; C = 512; g = gw; }
    else if (gw < 3072) { aw = a2w; ab = a2b; s = s2; C = 256; g = gw - 2048; }
    else                { aw = a3w; ab = a3b; s = s3; C = 256; g = gw - 3072; }
    int b = g / C, c = g - b * C;
    const float* wr = w + b * WD;
    const float* ar = aw + (size_t)c * WD;
    float acc = 0.f;
#pragma unroll
    for (int k = 0; k < WD / 32; k++) acc += wr[lane + 32 * k] * ar[lane + 32 * k];
#pragma unroll
    for (int o = 16; o; o >>= 1) acc += __shfl_xor_sync(~0u, acc, o);
    if (!lane) s[g] = acc + ab[c];
}

__global__ void wsq_all(const float* __restrict__ w1, const float* __restrict__ w2,
                        float* __restrict__ wsq1, float* __restrict__ wsq2) {
    int i = blockIdx.x * blockDim.x + threadIdx.x;
    const float* w; float* o; int j;
    if (i < 256 * 512) { w = w1; o = wsq1; j = i; }
    else if (i < 256 * 512 + 256 * 256) { w = w2; o = wsq2; j = i - 256 * 512; }
    else return;
    float a = 0.f;
#pragma unroll
    for (int k = 0; k < 9; k++) { float v = w[(size_t)j * 9 + k]; a += v * v; }
    o[j] = a;
}

__global__ void demod_all(const float* __restrict__ s1, const float* __restrict__ wsq1,
                          const float* __restrict__ s2, const float* __restrict__ wsq2,
                          float* __restrict__ d1, float* __restrict__ d2) {
    int gw = (blockIdx.x * blockDim.x + threadIdx.x) >> 5;
    int lane = threadIdx.x & 31;
    const float* s; const float* wsq; float* d; int Cin; int g;
    if (gw < 1024) { s = s1; wsq = wsq1; d = d1; Cin = 512; g = gw; }
    else           { s = s2; wsq = wsq2; d = d2; Cin = 256; g = gw - 1024; }
    int b = g >> 8, co = g & 255;
    const float* sr = s + b * Cin;
    const float* wr = wsq + (size_t)co * Cin;
    float acc = 0.f;
    for (int c = lane; c < Cin; c += 32) { float sv = sr[c]; acc += sv * sv * wr[c]; }
#pragma unroll
    for (int o = 16; o; o >>= 1) acc += __shfl_xor_sync(~0u, acc, o);
    if (!lane) d[g] = rsqrtf(acc + 1e-8f);
}

// prepack conv weights [tap][co][ci] fp16 + premodulated rgb weights fp32
__global__ void pack_all(const float* __restrict__ w1, const float* __restrict__ w2,
                         const float* __restrict__ w3, const float* __restrict__ s3,
                         __half* __restrict__ wpk1, __half* __restrict__ wpk2,
                         float* __restrict__ wm3) {
    int i = blockIdx.x * 256 + threadIdx.x;
    if (i < 9 * 256 * 512) {
        int ci = i & 511; int t = i >> 9; int co = t & 255; int tap = t >> 8;
        wpk1[i] = __float2half_rn(w1[((size_t)co * 512 + ci) * 9 + tap]);
    } else if (i < 9 * 256 * 512 + 9 * 256 * 256) {
        int j = i - 9 * 256 * 512;
        int ci = j & 255; int t = j >> 8; int co = t & 255; int tap = t >> 8;
        wpk2[j] = __float2half_rn(w2[((size_t)co * 256 + ci) * 9 + tap]);
    } else {
        int j = i - 9 * 256 * 512 - 9 * 256 * 256;
        if (j < B_ * 3 * 256) {
            int c = j & 255; int t = j >> 8; int r = t % 3; int b = t / 3;
            wm3[j] = w3[r * 256 + c] * s3[b * 256 + c];
        }
    }
}

// bilinear 2x upsample (half-pixel, edge clamp) * s1 -> padded NHWC fp16
__global__ void __launch_bounds__(256)
upmod_kernel(const float* __restrict__ x, const float* __restrict__ s1,
             __half* __restrict__ out) {
    __shared__ float st[2][32][21];
    const int tid = threadIdx.x;
    const int x0 = blockIdx.x * 32;
    const int y  = blockIdx.y;
    const int b  = blockIdx.z >> 4;
    const int ci0 = (blockIdx.z & 15) * 32;
    const int y0i = (y - 1) >> 1;
    const int yrow[2] = { max(y0i, 0), min(y0i + 1, 63) };
    const float fy = (y & 1) ? 0.25f : 0.75f;
    const int xs0 = (x0 >> 1) - 1;
    for (int t = tid; t < 32 * 2 * 18; t += 256) {
        int xi = t % 18;
        int rr = (t / 18) & 1;
        int ci = t / 36;
        int xs = min(max(xs0 + xi, 0), 63);
        st[rr][ci][xi] = x[(((size_t)b * 512 + ci0 + ci) * 64 + yrow[rr]) * 64 + xs];
    }
    __syncthreads();
    const int ci = tid & 31;
    const int jg = tid >> 5;
    const float sv = s1[b * 512 + ci0 + ci];
    __half* ob = out + (((size_t)b * 130 + 1 + y) * 130 + 1 + x0) * 512 + ci0 + ci;
#pragma unroll
    for (int q = 0; q < 4; q++) {
        int j = jg * 4 + q;
        int xi = (j + 1) >> 1;
        float fx = (j & 1) ? 0.25f : 0.75f;
        float v0 = st[0][ci][xi] * (1.f - fx) + st[0][ci][xi + 1] * fx;
        float v1 = st[1][ci][xi] * (1.f - fx) + st[1][ci][xi + 1] * fx;
        ob[(size_t)j * 512] = __float2half_rn((v0 * (1.f - fy) + v1 * fy) * sv);
    }
}

// ---------------- fp16 mma.sync implicit-GEMM 3x3 conv --------------------
// CTA: M = 256 pixels (2 rows of 128, blockIdx.x), N = 128 co (blockIdx.y), b = z.
// 8 warps = 4(M) x 2(N), warp tile 64x64 via m16n8k16 (K=32 ci per chunk, 2 steps).
// smem rows: 32 halves padded to 40 (80B) -> fragment LDS conflict-free.
// 3-stage cp.async pipeline, one __syncthreads per chunk.
template<int CIN, bool NHWC_OUT>
__global__ void __launch_bounds__(256, 1)
conv3x3_mma(const __half* __restrict__ in, const __half* __restrict__ wpk,
            const float* __restrict__ bias, const float* __restrict__ demod,
            const float* __restrict__ postscale,
            __half* __restrict__ outh, float* __restrict__ outf) {
    constexpr int CPT = CIN / 32;
    constexpr int NCH = 9 * CPT;
    constexpr int PADIN = 130;
    constexpr int SROW = 40;                 // halves per smem row (32 data + 8 pad)
    constexpr int ACT_H = 256 * SROW;        // halves per act stage
    constexpr int W_H   = 128 * SROW;
    extern __shared__ __half smh[];
    const uint32_t smb = smem_u32(smh);

    const int tid = threadIdx.x;
    const int wid = tid >> 5, lane = tid & 31;
    const int gq = lane >> 2, tg = lane & 3;
    const int wm = wid >> 1;
    const int wn = wid & 1;
    const int y0 = blockIdx.x * 2;
    const int co0 = blockIdx.y * 128;
    const int b  = blockIdx.z;

    float acc[4][8][4];
#pragma unroll
    for (int mi = 0; mi < 4; mi++)
#pragma unroll
        for (int ni = 0; ni < 8; ni++)
#pragma unroll
            for (int k = 0; k < 4; k++) acc[mi][ni][k] = 0.f;

    auto issue = [&](int i) {
        const int s = i % 3;
        const int tap = i / CPT;
        const int cc = (i - tap * CPT) * 32;
        const int dy = tap / 3 - 1, dx = tap % 3 - 1;
        const __half* abase = in + ((((size_t)b * PADIN + (y0 + dy + 1)) * PADIN + (1 + dx)) * CIN + cc);
        const uint32_t adst = smb + s * (ACT_H * 2);
        // act: 256 rows x 64B = 1024 x 16B chunks
#pragma unroll
        for (int r = 0; r < 4; r++) {
            int t = tid + r * 256;
            int row = t >> 2, j = t & 3;
            const __half* src = abase + (size_t)(row >> 7) * (PADIN * CIN) + (size_t)(row & 127) * CIN + j * 8;
            cp16(adst + (uint32_t)(row * SROW + j * 8) * 2, src);
        }
        // wgt: 128 rows x 64B = 512 x 16B chunks
        const __half* wbase = wpk + ((size_t)(tap * 256 + co0)) * CIN + cc;
        const uint32_t wdst = smb + (3 * ACT_H + s * W_H) * 2;
#pragma unroll
        for (int r = 0; r < 2; r++) {
            int t = tid + r * 256;
            int row = t >> 2, j = t & 3;
            cp16(wdst + (uint32_t)(row * SROW + j * 8) * 2, wbase + (size_t)row * CIN + j * 8);
        }
        asm volatile("cp.async.commit_group;" ::: "memory");
    };

    const uint32_t* As32 = (const uint32_t*)smh;          // word view (2 halves/word)
    constexpr int SROW_W = SROW / 2;                      // 20 words per row

    issue(0);
    issue(1);
    for (int i = 0; i < NCH; i++) {
        const int s = i % 3;
        if (i + 1 < NCH) asm volatile("cp.async.wait_group 1;" ::: "memory");
        else             asm volatile("cp.async.wait_group 0;" ::: "memory");
        __syncthreads();
        if (i + 2 < NCH) issue(i + 2);

        const uint32_t* A_ = As32 + s * (ACT_H / 2);
        const uint32_t* W_ = As32 + (3 * ACT_H + s * W_H) / 2;
#pragma unroll
        for (int ks = 0; ks < 2; ks++) {
            const int kw = ks * 8;                        // word offset of k16 step
            uint32_t af[4][4];
#pragma unroll
            for (int mi = 0; mi < 4; mi++) {
                const int row = wm * 64 + mi * 16 + gq;
                af[mi][0] = A_[row * SROW_W + kw + tg];
                af[mi][1] = A_[(row + 8) * SROW_W + kw + tg];
                af[mi][2] = A_[row * SROW_W + kw + tg + 4];
                af[mi][3] = A_[(row + 8) * SROW_W + kw + tg + 4];
            }
#pragma unroll
            for (int ni = 0; ni < 8; ni++) {
                const int n = wn * 64 + ni * 8 + gq;
                uint32_t bf[2];
                bf[0] = W_[n * SROW_W + kw + tg];
                bf[1] = W_[n * SROW_W + kw + tg + 4];
#pragma unroll
                for (int mi = 0; mi < 4; mi++) mma_f16(acc[mi][ni], af[mi], bf);
            }
        }
    }

    // epilogue
#pragma unroll
    for (int ni = 0; ni < 8; ni++) {
        const int co = co0 + wn * 64 + ni * 8 + 2 * tg;
        const float dm0 = demod[b * 256 + co],  dm1 = demod[b * 256 + co + 1];
        const float bi0 = bias[co],             bi1 = bias[co + 1];
        float ps0 = 1.f, ps1 = 1.f;
        if (NHWC_OUT) { ps0 = postscale[b * 256 + co]; ps1 = postscale[b * 256 + co + 1]; }
#pragma unroll
        for (int mi = 0; mi < 4; mi++) {
#pragma unroll
            for (int h = 0; h < 2; h++) {
                const int m = wm * 64 + mi * 16 + gq + h * 8;
                const int y = y0 + (m >> 7), xx = m & 127;
                float v0 = acc[mi][ni][2 * h + 0] * dm0 + bi0;
                float v1 = acc[mi][ni][2 * h + 1] * dm1 + bi1;
                v0 = v0 > 0.f ? v0 : LRELU_S * v0;
                v1 = v1 > 0.f ? v1 : LRELU_S * v1;
                if (NHWC_OUT) {
                    __half2 o = __floats2half2_rn(v0 * ps0, v1 * ps1);
                    *(__half2*)(outh + (((size_t)b * 130 + 1 + y) * 130 + 1 + xx) * 256 + co) = o;
                } else {
                    outf[(((size_t)b * 256 + co)     * 128 + y) * 128 + xx] = v0;
                    outf[(((size_t)b * 256 + co + 1) * 128 + y) * 128 + xx] = v1;
                }
            }
        }
    }
}

// rgb from NCHW h: pixel per thread, coalesced per-ci loads
__global__ void __launch_bounds__(256)
rgb_nchw(const float* __restrict__ h, const float* __restrict__ wm3,
         const float* __restrict__ b3, float* __restrict__ rgb) {
    const int idx = blockIdx.x * 256 + threadIdx.x;
    const int b = idx >> 14, pix = idx & 16383;
    const float* hp = h + (size_t)b * 256 * 16384 + pix;
    const float* wp = wm3 + b * 768;
    float a0 = 0.f, a1 = 0.f, a2 = 0.f;
#pragma unroll 4
    for (int c = 0; c < 256; c++) {
        float hv = hp[(size_t)c * 16384];
        a0 += wp[c] * hv;
        a1 += wp[256 + c] * hv;
        a2 += wp[512 + c] * hv;
    }
    float r0 = a0 + b3[0]; r0 = r0 > 0.f ? r0 : LRELU_S * r0;
    float r1 = a1 + b3[1]; r1 = r1 > 0.f ? r1 : LRELU_S * r1;
    float r2 = a2 + b3[2]; r2 = r2 > 0.f ? r2 : LRELU_S * r2;
    rgb[((size_t)b * 3 + 0) * 16384 + pix] = r0;
    rgb[((size_t)b * 3 + 1) * 16384 + pix] = r1;
    rgb[((size_t)b * 3 + 2) * 16384 + pix] = r2;
}

extern "C" void kernel_launch(void* const* d_in, const int* in_sizes, int n_in,
                              void* d_out, int out_size) {
    const float* x   = (const float*)d_in[0];
    const float* w   = (const float*)d_in[1];
    const float* w1  = (const float*)d_in[2];
    const float* b1  = (const float*)d_in[3];
    const float* a1w = (const float*)d_in[4];
    const float* a1b = (const float*)d_in[5];
    const float* w2  = (const float*)d_in[6];
    const float* b2  = (const float*)d_in[7];
    const float* a2w = (const float*)d_in[8];
    const float* a2b = (const float*)d_in[9];
    const float* w3  = (const float*)d_in[10];
    const float* b3  = (const float*)d_in[11];
    const float* a3w = (const float*)d_in[12];
    const float* a3b = (const float*)d_in[13];

    float* out_h   = (float*)d_out;
    float* out_rgb = out_h + (size_t)B_ * COUT * HW * HW;

    __half *xum, *h1m, *wpk1, *wpk2;
    float *s1, *s2, *s3, *d1, *d2, *wsq1, *wsq2, *wm3;
    cudaGetSymbolAddress((void**)&xum,  g_xum);
    cudaGetSymbolAddress((void**)&h1m,  g_h1m);
    cudaGetSymbolAddress((void**)&s1,   g_s1);
    cudaGetSymbolAddress((void**)&s2,   g_s2);
    cudaGetSymbolAddress((void**)&s3,   g_s3);
    cudaGetSymbolAddress((void**)&d1,   g_d1);
    cudaGetSymbolAddress((void**)&d2,   g_d2);
    cudaGetSymbolAddress((void**)&wsq1, g_wsq1);
    cudaGetSymbolAddress((void**)&wsq2, g_wsq2);
    cudaGetSymbolAddress((void**)&wpk1, g_wpk1);
    cudaGetSymbolAddress((void**)&wpk2, g_wpk2);
    cudaGetSymbolAddress((void**)&wm3,  g_wm3);

    const int SMEM_DYN = (3 * 256 * 40 + 3 * 128 * 40) * 2;   // 92160 B
    cudaFuncSetAttribute(conv3x3_mma<512, true>,
                         cudaFuncAttributeMaxDynamicSharedMemorySize, SMEM_DYN);
    cudaFuncSetAttribute(conv3x3_mma<256, false>,
                         cudaFuncAttributeMaxDynamicSharedMemorySize, SMEM_DYN);

    style_all<<<512, 256>>>(w, a1w, a1b, a2w, a2b, a3w, a3b, s1, s2, s3);
    wsq_all<<<(256 * 512 + 256 * 256 + 255) / 256, 256>>>(w1, w2, wsq1, wsq2);
    demod_all<<<256, 256>>>(s1, wsq1, s2, wsq2, d1, d2);
    pack_all<<<(9 * 256 * 512 + 9 * 256 * 256 + B_ * 3 * 256 + 255) / 256, 256>>>(
        w1, w2, w3, s3, wpk1, wpk2, wm3);

    upmod_kernel<<<dim3(4, 128, 64), 256>>>(x, s1, xum);

    // conv1: 512->256, epi *d1+b1, lrelu, *s2 -> h1m (padded NHWC fp16)
    conv3x3_mma<512, true><<<dim3(64, 2, 4), 256, SMEM_DYN>>>(xum, wpk1, b1, d1, s2,
                                                              h1m, (float*)nullptr);
    // conv2: 256->256, epi *d2+b2, lrelu -> out_h (NCHW fp32)
    conv3x3_mma<256, false><<<dim3(64, 2, 4), 256, SMEM_DYN>>>(h1m, wpk2, b2, d2,
                                                               (const float*)nullptr,
                                                               (__half*)nullptr, out_h);
    rgb_nchw<<<(B_ * HW * HW) / 256, 256>>>(out_h, wm3, b3, out_rgb);
}

// round 8
// speedup vs baseline: 1.6411x; 1.1515x over previous
#include <cuda_runtime.h>
#include <cuda_fp16.h>
#include <cstdint>

#define B_       4
#define COUT     256
#define HW       128
#define WD       512
#define LRELU_S  0.2f

// ---------------- device scratch (zero-initialized; borders stay zero) ----
__device__ __half g_xum[B_ * 130 * 130 * 512];  // padded NHWC fp16, premod s1
__device__ __half g_h1m[B_ * 130 * 130 * 256];  // padded NHWC fp16, premod s2
__device__ __half g_wpk1[9 * 256 * 512];        // [tap][co][ci] fp16
__device__ __half g_wpk2[9 * 256 * 256];
__device__ float g_wm3[B_ * 3 * 256];           // rgb weights premod s3
__device__ float g_s1[B_ * 512];
__device__ float g_s2[B_ * 256];
__device__ float g_s3[B_ * 256];
__device__ float g_d1[B_ * 256];
__device__ float g_d2[B_ * 256];
__device__ float g_wsq1[256 * 512];
__device__ float g_wsq2[256 * 256];

// ---------------- helpers -------------------------------------------------
__device__ __forceinline__ uint32_t smem_u32(const void* p) {
    uint32_t a;
    asm("{ .reg .u64 t; cvta.to.shared.u64 t, %1; cvt.u32.u64 %0, t; }" : "=r"(a) : "l"(p));
    return a;
}
__device__ __forceinline__ void cp16(uint32_t dst, const void* src) {
    asm volatile("cp.async.ca.shared.global [%0], [%1], 16;" :: "r"(dst), "l"(src));
}
__device__ __forceinline__ void ldsm_x4(uint32_t* r, uint32_t addr) {
    asm volatile("ldmatrix.sync.aligned.m8n8.x4.shared.b16 {%0,%1,%2,%3}, [%4];"
                 : "=r"(r[0]), "=r"(r[1]), "=r"(r[2]), "=r"(r[3]) : "r"(addr));
}
__device__ __forceinline__ void mma_f16(float* c, const uint32_t* a, const uint32_t* b) {
    asm volatile(
        "mma.sync.aligned.m16n8k16.row.col.f32.f16.f16.f32 "
        "{%0,%1,%2,%3}, {%4,%5,%6,%7}, {%8,%9}, {%0,%1,%2,%3};"
        : "+f"(c[0]), "+f"(c[1]), "+f"(c[2]), "+f"(c[3])
        : "r"(a[0]), "r"(a[1]), "r"(a[2]), "r"(a[3]), "r"(b[0]), "r"(b[1]));
}

// ---------------- merged prep kernels ------------------------------------
__global__ void style_all(const float* __restrict__ w,
                          const float* __restrict__ a1w, const float* __restrict__ a1b,
                          const float* __restrict__ a2w, const float* __restrict__ a2b,
                          const float* __restrict__ a3w, const float* __restrict__ a3b,
                          float* __restrict__ s1, float* __restrict__ s2,
                          float* __restrict__ s3) {
    int gw = (blockIdx.x * blockDim.x + threadIdx.x) >> 5;
    int lane = threadIdx.x & 31;
    const float* aw; const float* ab; float* s; int C; int g;
    if (gw < 2048)      { aw = a1w; ab = a1b; s = s1; C = 512; g = gw; }
    else if (gw < 3072) { aw = a2w; ab = a2b; s = s2; C = 256; g = gw - 2048; }
    else                { aw = a3w; ab = a3b; s = s3; C = 256; g = gw - 3072; }
    int b = g / C, c = g - b * C;
    const float* wr = w + b * WD;
    const float* ar = aw + (size_t)c * WD;
    float acc = 0.f;
#pragma unroll
    for (int k = 0; k < WD / 32; k++) acc += wr[lane + 32 * k] * ar[lane + 32 * k];
#pragma unroll
    for (int o = 16; o; o >>= 1) acc += __shfl_xor_sync(~0u, acc, o);
    if (!lane) s[g] = acc + ab[c];
}

__global__ void wsq_all(const float* __restrict__ w1, const float* __restrict__ w2,
                        float* __restrict__ wsq1, float* __restrict__ wsq2) {
    int i = blockIdx.x * blockDim.x + threadIdx.x;
    const float* w; float* o; int j;
    if (i < 256 * 512) { w = w1; o = wsq1; j = i; }
    else if (i < 256 * 512 + 256 * 256) { w = w2; o = wsq2; j = i - 256 * 512; }
    else return;
    float a = 0.f;
#pragma unroll
    for (int k = 0; k < 9; k++) { float v = w[(size_t)j * 9 + k]; a += v * v; }
    o[j] = a;
}

__global__ void demod_all(const float* __restrict__ s1, const float* __restrict__ wsq1,
                          const float* __restrict__ s2, const float* __restrict__ wsq2,
                          float* __restrict__ d1, float* __restrict__ d2) {
    int gw = (blockIdx.x * blockDim.x + threadIdx.x) >> 5;
    int lane = threadIdx.x & 31;
    const float* s; const float* wsq; float* d; int Cin; int g;
    if (gw < 1024) { s = s1; wsq = wsq1; d = d1; Cin = 512; g = gw; }
    else           { s = s2; wsq = wsq2; d = d2; Cin = 256; g = gw - 1024; }
    int b = g >> 8, co = g & 255;
    const float* sr = s + b * Cin;
    const float* wr = wsq + (size_t)co * Cin;
    float acc = 0.f;
    for (int c = lane; c < Cin; c += 32) { float sv = sr[c]; acc += sv * sv * wr[c]; }
#pragma unroll
    for (int o = 16; o; o >>= 1) acc += __shfl_xor_sync(~0u, acc, o);
    if (!lane) d[g] = rsqrtf(acc + 1e-8f);
}

__global__ void pack_all(const float* __restrict__ w1, const float* __restrict__ w2,
                         const float* __restrict__ w3, const float* __restrict__ s3,
                         __half* __restrict__ wpk1, __half* __restrict__ wpk2,
                         float* __restrict__ wm3) {
    int i = blockIdx.x * 256 + threadIdx.x;
    if (i < 9 * 256 * 512) {
        int ci = i & 511; int t = i >> 9; int co = t & 255; int tap = t >> 8;
        wpk1[i] = __float2half_rn(w1[((size_t)co * 512 + ci) * 9 + tap]);
    } else if (i < 9 * 256 * 512 + 9 * 256 * 256) {
        int j = i - 9 * 256 * 512;
        int ci = j & 255; int t = j >> 8; int co = t & 255; int tap = t >> 8;
        wpk2[j] = __float2half_rn(w2[((size_t)co * 256 + ci) * 9 + tap]);
    } else {
        int j = i - 9 * 256 * 512 - 9 * 256 * 256;
        if (j < B_ * 3 * 256) {
            int c = j & 255; int t = j >> 8; int r = t % 3; int b = t / 3;
            wm3[j] = w3[r * 256 + c] * s3[b * 256 + c];
        }
    }
}

// bilinear 2x upsample (half-pixel, edge clamp) * s1 -> padded NHWC fp16
__global__ void __launch_bounds__(256)
upmod_kernel(const float* __restrict__ x, const float* __restrict__ s1,
             __half* __restrict__ out) {
    __shared__ float st[2][32][21];
    const int tid = threadIdx.x;
    const int x0 = blockIdx.x * 32;
    const int y  = blockIdx.y;
    const int b  = blockIdx.z >> 4;
    const int ci0 = (blockIdx.z & 15) * 32;
    const int y0i = (y - 1) >> 1;
    const int yrow[2] = { max(y0i, 0), min(y0i + 1, 63) };
    const float fy = (y & 1) ? 0.25f : 0.75f;
    const int xs0 = (x0 >> 1) - 1;
    for (int t = tid; t < 32 * 2 * 18; t += 256) {
        int xi = t % 18;
        int rr = (t / 18) & 1;
        int ci = t / 36;
        int xs = min(max(xs0 + xi, 0), 63);
        st[rr][ci][xi] = x[(((size_t)b * 512 + ci0 + ci) * 64 + yrow[rr]) * 64 + xs];
    }
    __syncthreads();
    const int ci = tid & 31;
    const int jg = tid >> 5;
    const float sv = s1[b * 512 + ci0 + ci];
    __half* ob = out + (((size_t)b * 130 + 1 + y) * 130 + 1 + x0) * 512 + ci0 + ci;
#pragma unroll
    for (int q = 0; q < 4; q++) {
        int j = jg * 4 + q;
        int xi = (j + 1) >> 1;
        float fx = (j & 1) ? 0.25f : 0.75f;
        float v0 = st[0][ci][xi] * (1.f - fx) + st[0][ci][xi + 1] * fx;
        float v1 = st[1][ci][xi] * (1.f - fx) + st[1][ci][xi + 1] * fx;
        ob[(size_t)j * 512] = __float2half_rn((v0 * (1.f - fy) + v1 * fy) * sv);
    }
}

// ---------------- fp16 mma implicit-GEMM 3x3 conv, ldmatrix + 2 CTA/SM ----
// CTA: M = 256 px (2 rows of 128), N = 64 co. 8 warps = 4(M) x 2(N),
// warp tile 64x32. grid (64, 4, B). 3-stage cp.async, 1 barrier/chunk.
// smem rows: 32 ci halves + 8 pad = 80B; LDSM-verified conflict-free.
template<int CIN, bool NHWC_OUT>
__global__ void __launch_bounds__(256, 2)
conv3x3_mma(const __half* __restrict__ in, const __half* __restrict__ wpk,
            const float* __restrict__ bias, const float* __restrict__ demod,
            const float* __restrict__ postscale,
            __half* __restrict__ outh, float* __restrict__ outf) {
    constexpr int CPT = CIN / 32;
    constexpr int NCH = 9 * CPT;
    constexpr int PADIN = 130;
    constexpr int SROW = 40;                 // halves per smem row (80 B)
    constexpr int ACT_H = 256 * SROW;
    constexpr int W_H   = 64 * SROW;
    extern __shared__ __half smh[];
    const uint32_t smb = smem_u32(smh);

    const int tid = threadIdx.x;
    const int wid = tid >> 5, lane = tid & 31;
    const int gq = lane >> 2, tg = lane & 3;
    const int wm = wid >> 1;                 // 0..3 pixel quarter (64 px)
    const int wn = wid & 1;                  // 0..1 co half (32 co)
    const int y0 = blockIdx.x * 2;
    const int co0 = blockIdx.y * 64;
    const int b  = blockIdx.z;

    float acc[4][4][4];
#pragma unroll
    for (int mi = 0; mi < 4; mi++)
#pragma unroll
        for (int ni = 0; ni < 4; ni++)
#pragma unroll
            for (int k = 0; k < 4; k++) acc[mi][ni][k] = 0.f;

    auto issue = [&](int i) {
        const int s = i % 3;
        const int tap = i / CPT;
        const int cc = (i - tap * CPT) * 32;
        const int dy = tap / 3 - 1, dx = tap % 3 - 1;
        const __half* abase = in + ((((size_t)b * PADIN + (y0 + dy + 1)) * PADIN + (1 + dx)) * CIN + cc);
        const uint32_t adst = smb + s * (ACT_H * 2);
#pragma unroll
        for (int r = 0; r < 4; r++) {        // act: 256 rows x 64B
            int t = tid + r * 256;
            int row = t >> 2, j = t & 3;
            const __half* src = abase + (size_t)(row >> 7) * (PADIN * CIN) + (size_t)(row & 127) * CIN + j * 8;
            cp16(adst + (uint32_t)(row * SROW + j * 8) * 2, src);
        }
        const __half* wbase = wpk + ((size_t)(tap * 256 + co0)) * CIN + cc;
        const uint32_t wdst = smb + (3 * ACT_H + s * W_H) * 2;
        {                                    // wgt: 64 rows x 64B = 256 chunks
            int row = tid >> 2, j = tid & 3;
            cp16(wdst + (uint32_t)(row * SROW + j * 8) * 2, wbase + (size_t)row * CIN + j * 8);
        }
        asm volatile("cp.async.commit_group;" ::: "memory");
    };

    // ldmatrix lane->address components
    const int a_row = lane & 15;             // A: row within 16, col16 = lane>>4
    const int a_c16 = lane >> 4;
    const int b_row = (lane & 7) + ((lane >> 4) << 3);   // B: row within 16
    const int b_c16 = (lane >> 3) & 1;

    issue(0);
    issue(1);
    for (int i = 0; i < NCH; i++) {
        const int s = i % 3;
        if (i + 1 < NCH) asm volatile("cp.async.wait_group 1;" ::: "memory");
        else             asm volatile("cp.async.wait_group 0;" ::: "memory");
        __syncthreads();
        if (i + 2 < NCH) issue(i + 2);

        const uint32_t aS = smb + s * (ACT_H * 2);
        const uint32_t wS = smb + (3 * ACT_H + s * W_H) * 2;
#pragma unroll
        for (int ks = 0; ks < 2; ks++) {
            uint32_t af[4][4];
#pragma unroll
            for (int mi = 0; mi < 4; mi++)
                ldsm_x4(af[mi], aS + (uint32_t)(wm * 64 + mi * 16 + a_row) * 80
                                   + a_c16 * 16 + ks * 32);
            uint32_t bf[8];
#pragma unroll
            for (int nb = 0; nb < 2; nb++)
                ldsm_x4(bf + nb * 4, wS + (uint32_t)(wn * 32 + nb * 16 + b_row) * 80
                                        + b_c16 * 16 + ks * 32);
#pragma unroll
            for (int ni = 0; ni < 4; ni++) {
                const uint32_t* bp = bf + (ni >> 1) * 4 + (ni & 1) * 2;
#pragma unroll
                for (int mi = 0; mi < 4; mi++) mma_f16(acc[mi][ni], af[mi], bp);
            }
        }
    }

    // epilogue: c0,c1 = (row gq, col 2tg/2tg+1); c2,c3 = row gq+8
#pragma unroll
    for (int ni = 0; ni < 4; ni++) {
        const int co = co0 + wn * 32 + ni * 8 + 2 * tg;
        const float dm0 = demod[b * 256 + co],  dm1 = demod[b * 256 + co + 1];
        const float bi0 = bias[co],             bi1 = bias[co + 1];
        float ps0 = 1.f, ps1 = 1.f;
        if (NHWC_OUT) { ps0 = postscale[b * 256 + co]; ps1 = postscale[b * 256 + co + 1]; }
#pragma unroll
        for (int mi = 0; mi < 4; mi++) {
#pragma unroll
            for (int h = 0; h < 2; h++) {
                const int m = wm * 64 + mi * 16 + gq + h * 8;
                const int y = y0 + (m >> 7), xx = m & 127;
                float v0 = acc[mi][ni][2 * h + 0] * dm0 + bi0;
                float v1 = acc[mi][ni][2 * h + 1] * dm1 + bi1;
                v0 = v0 > 0.f ? v0 : LRELU_S * v0;
                v1 = v1 > 0.f ? v1 : LRELU_S * v1;
                if (NHWC_OUT) {
                    __half2 o = __floats2half2_rn(v0 * ps0, v1 * ps1);
                    *(__half2*)(outh + (((size_t)b * 130 + 1 + y) * 130 + 1 + xx) * 256 + co) = o;
                } else {
                    outf[(((size_t)b * 256 + co)     * 128 + y) * 128 + xx] = v0;
                    outf[(((size_t)b * 256 + co + 1) * 128 + y) * 128 + xx] = v1;
                }
            }
        }
    }
}

// rgb from NCHW h: pixel per thread, coalesced per-ci loads
__global__ void __launch_bounds__(256)
rgb_nchw(const float* __restrict__ h, const float* __restrict__ wm3,
         const float* __restrict__ b3, float* __restrict__ rgb) {
    const int idx = blockIdx.x * 256 + threadIdx.x;
    const int b = idx >> 14, pix = idx & 16383;
    const float* hp = h + (size_t)b * 256 * 16384 + pix;
    const float* wp = wm3 + b * 768;
    float a0 = 0.f, a1 = 0.f, a2 = 0.f;
#pragma unroll 4
    for (int c = 0; c < 256; c++) {
        float hv = hp[(size_t)c * 16384];
        a0 += wp[c] * hv;
        a1 += wp[256 + c] * hv;
        a2 += wp[512 + c] * hv;
    }
    float r0 = a0 + b3[0]; r0 = r0 > 0.f ? r0 : LRELU_S * r0;
    float r1 = a1 + b3[1]; r1 = r1 > 0.f ? r1 : LRELU_S * r1;
    float r2 = a2 + b3[2]; r2 = r2 > 0.f ? r2 : LRELU_S * r2;
    rgb[((size_t)b * 3 + 0) * 16384 + pix] = r0;
    rgb[((size_t)b * 3 + 1) * 16384 + pix] = r1;
    rgb[((size_t)b * 3 + 2) * 16384 + pix] = r2;
}

extern "C" void kernel_launch(void* const* d_in, const int* in_sizes, int n_in,
                              void* d_out, int out_size) {
    const float* x   = (const float*)d_in[0];
    const float* w   = (const float*)d_in[1];
    const float* w1  = (const float*)d_in[2];
    const float* b1  = (const float*)d_in[3];
    const float* a1w = (const float*)d_in[4];
    const float* a1b = (const float*)d_in[5];
    const float* w2  = (const float*)d_in[6];
    const float* b2  = (const float*)d_in[7];
    const float* a2w = (const float*)d_in[8];
    const float* a2b = (const float*)d_in[9];
    const float* w3  = (const float*)d_in[10];
    const float* b3  = (const float*)d_in[11];
    const float* a3w = (const float*)d_in[12];
    const float* a3b = (const float*)d_in[13];

    float* out_h   = (float*)d_out;
    float* out_rgb = out_h + (size_t)B_ * COUT * HW * HW;

    __half *xum, *h1m, *wpk1, *wpk2;
    float *s1, *s2, *s3, *d1, *d2, *wsq1, *wsq2, *wm3;
    cudaGetSymbolAddress((void**)&xum,  g_xum);
    cudaGetSymbolAddress((void**)&h1m,  g_h1m);
    cudaGetSymbolAddress((void**)&s1,   g_s1);
    cudaGetSymbolAddress((void**)&s2,   g_s2);
    cudaGetSymbolAddress((void**)&s3,   g_s3);
    cudaGetSymbolAddress((void**)&d1,   g_d1);
    cudaGetSymbolAddress((void**)&d2,   g_d2);
    cudaGetSymbolAddress((void**)&wsq1, g_wsq1);
    cudaGetSymbolAddress((void**)&wsq2, g_wsq2);
    cudaGetSymbolAddress((void**)&wpk1, g_wpk1);
    cudaGetSymbolAddress((void**)&wpk2, g_wpk2);
    cudaGetSymbolAddress((void**)&wm3,  g_wm3);

    const int SMEM_DYN = 3 * (256 * 40 + 64 * 40) * 2;   // 76800 B -> 2 CTAs/SM
    cudaFuncSetAttribute(conv3x3_mma<512, true>,
                         cudaFuncAttributeMaxDynamicSharedMemorySize, SMEM_DYN);
    cudaFuncSetAttribute(conv3x3_mma<256, false>,
                         cudaFuncAttributeMaxDynamicSharedMemorySize, SMEM_DYN);

    style_all<<<512, 256>>>(w, a1w, a1b, a2w, a2b, a3w, a3b, s1, s2, s3);
    wsq_all<<<(256 * 512 + 256 * 256 + 255) / 256, 256>>>(w1, w2, wsq1, wsq2);
    demod_all<<<256, 256>>>(s1, wsq1, s2, wsq2, d1, d2);
    pack_all<<<(9 * 256 * 512 + 9 * 256 * 256 + B_ * 3 * 256 + 255) / 256, 256>>>(
        w1, w2, w3, s3, wpk1, wpk2, wm3);

    upmod_kernel<<<dim3(4, 128, 64), 256>>>(x, s1, xum);

    // conv1: 512->256, epi *d1+b1, lrelu, *s2 -> h1m (padded NHWC fp16)
    conv3x3_mma<512, true><<<dim3(64, 4, 4), 256, SMEM_DYN>>>(xum, wpk1, b1, d1, s2,
                                                              h1m, (float*)nullptr);
    // conv2: 256->256, epi *d2+b2, lrelu -> out_h (NCHW fp32)
    conv3x3_mma<256, false><<<dim3(64, 4, 4), 256, SMEM_DYN>>>(h1m, wpk2, b2, d2,
                                                               (const float*)nullptr,
                                                               (__half*)nullptr, out_h);
    rgb_nchw<<<(B_ * HW * HW) / 256, 256>>>(out_h, wm3, b3, out_rgb);
}

// round 17
// speedup vs baseline: 1.7621x; 1.0738x over previous
#include <cuda_runtime.h>
#include <cuda_fp16.h>
#include <cstdint>

#define B_       4
#define COUT     256
#define HW       128
#define WD       512
#define LRELU_S  0.2f

// ---------------- device scratch (zero-initialized; borders stay zero) ----
__device__ __half g_xum[B_ * 130 * 130 * 512];  // padded NHWC fp16, premod s1
__device__ __half g_h1m[B_ * 130 * 130 * 256];  // padded NHWC fp16, premod s2
__device__ __half g_wpk1[9 * 256 * 512];        // [tap][co][ci] fp16
__device__ __half g_wpk2[9 * 256 * 256];
__device__ float g_wm3[B_ * 3 * 256];           // rgb weights premod s3
__device__ float g_s1[B_ * 512];
__device__ float g_s2[B_ * 256];
__device__ float g_s3[B_ * 256];
__device__ float g_d1[B_ * 256];
__device__ float g_d2[B_ * 256];
__device__ float g_wsq1[256 * 512];
__device__ float g_wsq2[256 * 256];

// ---------------- helpers -------------------------------------------------
__device__ __forceinline__ uint32_t smem_u32(const void* p) {
    uint32_t a;
    asm("{ .reg .u64 t; cvta.to.shared.u64 t, %1; cvt.u32.u64 %0, t; }" : "=r"(a) : "l"(p));
    return a;
}
__device__ __forceinline__ void cp16(uint32_t dst, const void* src) {
    asm volatile("cp.async.ca.shared.global [%0], [%1], 16;" :: "r"(dst), "l"(src));
}
__device__ __forceinline__ void ldsm_x4(uint32_t* r, uint32_t addr) {
    asm volatile("ldmatrix.sync.aligned.m8n8.x4.shared.b16 {%0,%1,%2,%3}, [%4];"
                 : "=r"(r[0]), "=r"(r[1]), "=r"(r[2]), "=r"(r[3]) : "r"(addr));
}
__device__ __forceinline__ void mma_f16(float* c, const uint32_t* a, const uint32_t* b) {
    asm volatile(
        "mma.sync.aligned.m16n8k16.row.col.f32.f16.f16.f32 "
        "{%0,%1,%2,%3}, {%4,%5,%6,%7}, {%8,%9}, {%0,%1,%2,%3};"
        : "+f"(c[0]), "+f"(c[1]), "+f"(c[2]), "+f"(c[3])
        : "r"(a[0]), "r"(a[1]), "r"(a[2]), "r"(a[3]), "r"(b[0]), "r"(b[1]));
}

// ---------------- prep kernel 1: styles + weight-square sums --------------
// blocks [0,512): styles (4096 warp-outputs); blocks [512,1280): wsq
__global__ void prep1(const float* __restrict__ w,
                      const float* __restrict__ a1w, const float* __restrict__ a1b,
                      const float* __restrict__ a2w, const float* __restrict__ a2b,
                      const float* __restrict__ a3w, const float* __restrict__ a3b,
                      const float* __restrict__ w1, const float* __restrict__ w2,
                      float* __restrict__ s1, float* __restrict__ s2,
                      float* __restrict__ s3,
                      float* __restrict__ wsq1, float* __restrict__ wsq2) {
    if (blockIdx.x < 512) {
        int gw = (blockIdx.x * 256 + threadIdx.x) >> 5;      // 0..4095
        int lane = threadIdx.x & 31;
        const float* aw; const float* ab; float* s; int C; int g;
        if (gw < 2048)      { aw = a1w; ab = a1b; s = s1; C = 512; g = gw; }
        else if (gw < 3072) { aw = a2w; ab = a2b; s = s2; C = 256; g = gw - 2048; }
        else                { aw = a3w; ab = a3b; s = s3; C = 256; g = gw - 3072; }
        int b = g / C, c = g - b * C;
        const float* wr = w + b * WD;
        const float* ar = aw + (size_t)c * WD;
        float acc = 0.f;
#pragma unroll
        for (int k = 0; k < WD / 32; k++) acc += wr[lane + 32 * k] * ar[lane + 32 * k];
#pragma unroll
        for (int o = 16; o; o >>= 1) acc += __shfl_xor_sync(~0u, acc, o);
        if (!lane) s[g] = acc + ab[c];
    } else {
        int i = (blockIdx.x - 512) * 256 + threadIdx.x;
        const float* wsrc; float* o; int j;
        if (i < 256 * 512) { wsrc = w1; o = wsq1; j = i; }
        else if (i < 256 * 512 + 256 * 256) { wsrc = w2; o = wsq2; j = i - 256 * 512; }
        else return;
        float a = 0.f;
#pragma unroll
        for (int k = 0; k < 9; k++) { float v = wsrc[(size_t)j * 9 + k]; a += v * v; }
        o[j] = a;
    }
}

// ---------------- prep kernel 2: demod + weight prepack -------------------
// blocks [0,256): demod (2048 warp-outputs); blocks [256,7180): prepack
__global__ void prep2(const float* __restrict__ s1, const float* __restrict__ wsq1,
                      const float* __restrict__ s2, const float* __restrict__ wsq2,
                      const float* __restrict__ w1, const float* __restrict__ w2,
                      const float* __restrict__ w3, const float* __restrict__ s3,
                      float* __restrict__ d1, float* __restrict__ d2,
                      __half* __restrict__ wpk1, __half* __restrict__ wpk2,
                      float* __restrict__ wm3) {
    if (blockIdx.x < 256) {
        int gw = (blockIdx.x * 256 + threadIdx.x) >> 5;      // 0..2047
        int lane = threadIdx.x & 31;
        const float* s; const float* wsq; float* d; int Cin; int g;
        if (gw < 1024) { s = s1; wsq = wsq1; d = d1; Cin = 512; g = gw; }
        else           { s = s2; wsq = wsq2; d = d2; Cin = 256; g = gw - 1024; }
        int b = g >> 8, co = g & 255;
        const float* sr = s + b * Cin;
        const float* wr = wsq + (size_t)co * Cin;
        float acc = 0.f;
        for (int c = lane; c < Cin; c += 32) { float sv = sr[c]; acc += sv * sv * wr[c]; }
#pragma unroll
        for (int o = 16; o; o >>= 1) acc += __shfl_xor_sync(~0u, acc, o);
        if (!lane) d[g] = rsqrtf(acc + 1e-8f);
    } else {
        int i = (blockIdx.x - 256) * 256 + threadIdx.x;
        if (i < 9 * 256 * 512) {
            int ci = i & 511; int t = i >> 9; int co = t & 255; int tap = t >> 8;
            wpk1[i] = __float2half_rn(w1[((size_t)co * 512 + ci) * 9 + tap]);
        } else if (i < 9 * 256 * 512 + 9 * 256 * 256) {
            int j = i - 9 * 256 * 512;
            int ci = j & 255; int t = j >> 8; int co = t & 255; int tap = t >> 8;
            wpk2[j] = __float2half_rn(w2[((size_t)co * 256 + ci) * 9 + tap]);
        } else {
            int j = i - 9 * 256 * 512 - 9 * 256 * 256;
            if (j < B_ * 3 * 256) {
                int c = j & 255; int t = j >> 8; int r = t % 3; int b = t / 3;
                wm3[j] = w3[r * 256 + c] * s3[b * 256 + c];
            }
        }
    }
}

// bilinear 2x upsample (half-pixel, edge clamp) * s1 -> padded NHWC fp16
__global__ void __launch_bounds__(256)
upmod_kernel(const float* __restrict__ x, const float* __restrict__ s1,
             __half* __restrict__ out) {
    __shared__ float st[2][32][21];
    const int tid = threadIdx.x;
    const int x0 = blockIdx.x * 32;
    const int y  = blockIdx.y;
    const int b  = blockIdx.z >> 4;
    const int ci0 = (blockIdx.z & 15) * 32;
    const int y0i = (y - 1) >> 1;
    const int yrow[2] = { max(y0i, 0), min(y0i + 1, 63) };
    const float fy = (y & 1) ? 0.25f : 0.75f;
    const int xs0 = (x0 >> 1) - 1;
    for (int t = tid; t < 32 * 2 * 18; t += 256) {
        int xi = t % 18;
        int rr = (t / 18) & 1;
        int ci = t / 36;
        int xs = min(max(xs0 + xi, 0), 63);
        st[rr][ci][xi] = x[(((size_t)b * 512 + ci0 + ci) * 64 + yrow[rr]) * 64 + xs];
    }
    __syncthreads();
    const int ci = tid & 31;
    const int jg = tid >> 5;
    const float sv = s1[b * 512 + ci0 + ci];
    __half* ob = out + (((size_t)b * 130 + 1 + y) * 130 + 1 + x0) * 512 + ci0 + ci;
#pragma unroll
    for (int q = 0; q < 4; q++) {
        int j = jg * 4 + q;
        int xi = (j + 1) >> 1;
        float fx = (j & 1) ? 0.25f : 0.75f;
        float v0 = st[0][ci][xi] * (1.f - fx) + st[0][ci][xi + 1] * fx;
        float v1 = st[1][ci][xi] * (1.f - fx) + st[1][ci][xi + 1] * fx;
        ob[(size_t)j * 512] = __float2half_rn((v0 * (1.f - fy) + v1 * fy) * sv);
    }
}

// ---------------- persistent fp16 mma implicit-GEMM 3x3 conv --------------
// Grid = 296 persistent CTAs (2/SM); each loops tiles t in [blockIdx; 1024; grid).
// Tile: M = 256 px (2 rows of 128), N = 64 co. 8 warps = 4(M) x 2(N),
// warp tile 64x32. 3-stage cp.async, 1 barrier/chunk (NCH % 3 == 0).
template<int CIN, bool NHWC_OUT>
__global__ void __launch_bounds__(256, 2)
conv3x3_mma(const __half* __restrict__ in, const __half* __restrict__ wpk,
            const float* __restrict__ bias, const float* __restrict__ demod,
            const float* __restrict__ postscale,
            __half* __restrict__ outh, float* __restrict__ outf) {
    constexpr int CPT = CIN / 32;
    constexpr int NCH = 9 * CPT;               // 144 or 72 (divisible by 3)
    constexpr int PADIN = 130;
    constexpr int SROW = 40;
    constexpr int ACT_H = 256 * SROW;
    constexpr int W_H   = 64 * SROW;
    constexpr int NT = 64 * 4 * B_;            // 1024 tiles
    extern __shared__ __half smh[];
    const uint32_t smb = smem_u32(smh);

    const int tid = threadIdx.x;
    const int wid = tid >> 5, lane = tid & 31;
    const int gq = lane >> 2, tg = lane & 3;
    const int wm = wid >> 1;
    const int wn = wid & 1;

    const int a_row = lane & 15;
    const int a_c16 = lane >> 4;
    const int b_row = (lane & 7) + ((lane >> 4) << 3);
    const int b_c16 = (lane >> 3) & 1;

    for (int t = blockIdx.x; t < NT; t += gridDim.x) {
        const int y0 = (t & 63) * 2;
        const int co0 = ((t >> 6) & 3) * 64;
        const int b  = t >> 8;

        float acc[4][4][4];
#pragma unroll
        for (int mi = 0; mi < 4; mi++)
#pragma unroll
            for (int ni = 0; ni < 4; ni++)
#pragma unroll
                for (int k = 0; k < 4; k++) acc[mi][ni][k] = 0.f;

        auto issue = [&](int i) {
            const int s = i % 3;
            const int tap = i / CPT;
            const int cc = (i - tap * CPT) * 32;
            const int dy = tap / 3 - 1, dx = tap % 3 - 1;
            const __half* abase = in + ((((size_t)b * PADIN + (y0 + dy + 1)) * PADIN + (1 + dx)) * CIN + cc);
            const uint32_t adst = smb + s * (ACT_H * 2);
#pragma unroll
            for (int r = 0; r < 4; r++) {
                int tt = tid + r * 256;
                int row = tt >> 2, j = tt & 3;
                const __half* src = abase + (size_t)(row >> 7) * (PADIN * CIN) + (size_t)(row & 127) * CIN + j * 8;
                cp16(adst + (uint32_t)(row * SROW + j * 8) * 2, src);
            }
            const __half* wbase = wpk + ((size_t)(tap * 256 + co0)) * CIN + cc;
            const uint32_t wdst = smb + (3 * ACT_H + s * W_H) * 2;
            {
                int row = tid >> 2, j = tid & 3;
                cp16(wdst + (uint32_t)(row * SROW + j * 8) * 2, wbase + (size_t)row * CIN + j * 8);
            }
            asm volatile("cp.async.commit_group;" ::: "memory");
        };

        issue(0);
        issue(1);
        for (int i = 0; i < NCH; i++) {
            const int s = i % 3;
            if (i + 1 < NCH) asm volatile("cp.async.wait_group 1;" ::: "memory");
            else             asm volatile("cp.async.wait_group 0;" ::: "memory");
            __syncthreads();
            if (i + 2 < NCH) issue(i + 2);

            const uint32_t aS = smb + s * (ACT_H * 2);
            const uint32_t wS = smb + (3 * ACT_H + s * W_H) * 2;
#pragma unroll
            for (int ks = 0; ks < 2; ks++) {
                uint32_t af[4][4];
#pragma unroll
                for (int mi = 0; mi < 4; mi++)
                    ldsm_x4(af[mi], aS + (uint32_t)(wm * 64 + mi * 16 + a_row) * 80
                                       + a_c16 * 16 + ks * 32);
                uint32_t bf[8];
#pragma unroll
                for (int nb = 0; nb < 2; nb++)
                    ldsm_x4(bf + nb * 4, wS + (uint32_t)(wn * 32 + nb * 16 + b_row) * 80
                                            + b_c16 * 16 + ks * 32);
#pragma unroll
                for (int ni = 0; ni < 4; ni++) {
                    const uint32_t* bp = bf + (ni >> 1) * 4 + (ni & 1) * 2;
#pragma unroll
                    for (int mi = 0; mi < 4; mi++) mma_f16(acc[mi][ni], af[mi], bp);
                }
            }
        }

        // epilogue (no smem — safe against next tile's prefetch)
#pragma unroll
        for (int ni = 0; ni < 4; ni++) {
            const int co = co0 + wn * 32 + ni * 8 + 2 * tg;
            const float dm0 = demod[b * 256 + co],  dm1 = demod[b * 256 + co + 1];
            const float bi0 = bias[co],             bi1 = bias[co + 1];
            float ps0 = 1.f, ps1 = 1.f;
            if (NHWC_OUT) { ps0 = postscale[b * 256 + co]; ps1 = postscale[b * 256 + co + 1]; }
#pragma unroll
            for (int mi = 0; mi < 4; mi++) {
#pragma unroll
                for (int h = 0; h < 2; h++) {
                    const int m = wm * 64 + mi * 16 + gq + h * 8;
                    const int y = y0 + (m >> 7), xx = m & 127;
                    float v0 = acc[mi][ni][2 * h + 0] * dm0 + bi0;
                    float v1 = acc[mi][ni][2 * h + 1] * dm1 + bi1;
                    v0 = v0 > 0.f ? v0 : LRELU_S * v0;
                    v1 = v1 > 0.f ? v1 : LRELU_S * v1;
                    if (NHWC_OUT) {
                        __half2 o = __floats2half2_rn(v0 * ps0, v1 * ps1);
                        *(__half2*)(outh + (((size_t)b * 130 + 1 + y) * 130 + 1 + xx) * 256 + co) = o;
                    } else {
                        outf[(((size_t)b * 256 + co)     * 128 + y) * 128 + xx] = v0;
                        outf[(((size_t)b * 256 + co + 1) * 128 + y) * 128 + xx] = v1;
                    }
                }
            }
        }
        __syncthreads();   // all epilogue acc reads done before next tile reuses smem pipeline
    }
}

// rgb from NCHW h: pixel per thread, coalesced per-ci loads
__global__ void __launch_bounds__(256)
rgb_nchw(const float* __restrict__ h, const float* __restrict__ wm3,
         const float* __restrict__ b3, float* __restrict__ rgb) {
    const int idx = blockIdx.x * 256 + threadIdx.x;
    const int b = idx >> 14, pix = idx & 16383;
    const float* hp = h + (size_t)b * 256 * 16384 + pix;
    const float* wp = wm3 + b * 768;
    float a0 = 0.f, a1 = 0.f, a2 = 0.f;
#pragma unroll 4
    for (int c = 0; c < 256; c++) {
        float hv = hp[(size_t)c * 16384];
        a0 += wp[c] * hv;
        a1 += wp[256 + c] * hv;
        a2 += wp[512 + c] * hv;
    }
    float r0 = a0 + b3[0]; r0 = r0 > 0.f ? r0 : LRELU_S * r0;
    float r1 = a1 + b3[1]; r1 = r1 > 0.f ? r1 : LRELU_S * r1;
    float r2 = a2 + b3[2]; r2 = r2 > 0.f ? r2 : LRELU_S * r2;
    rgb[((size_t)b * 3 + 0) * 16384 + pix] = r0;
    rgb[((size_t)b * 3 + 1) * 16384 + pix] = r1;
    rgb[((size_t)b * 3 + 2) * 16384 + pix] = r2;
}

extern "C" void kernel_launch(void* const* d_in, const int* in_sizes, int n_in,
                              void* d_out, int out_size) {
    const float* x   = (const float*)d_in[0];
    const float* w   = (const float*)d_in[1];
    const float* w1  = (const float*)d_in[2];
    const float* b1  = (const float*)d_in[3];
    const float* a1w = (const float*)d_in[4];
    const float* a1b = (const float*)d_in[5];
    const float* w2  = (const float*)d_in[6];
    const float* b2  = (const float*)d_in[7];
    const float* a2w = (const float*)d_in[8];
    const float* a2b = (const float*)d_in[9];
    const float* w3  = (const float*)d_in[10];
    const float* b3  = (const float*)d_in[11];
    const float* a3w = (const float*)d_in[12];
    const float* a3b = (const float*)d_in[13];

    float* out_h   = (float*)d_out;
    float* out_rgb = out_h + (size_t)B_ * COUT * HW * HW;

    __half *xum, *h1m, *wpk1, *wpk2;
    float *s1, *s2, *s3, *d1, *d2, *wsq1, *wsq2, *wm3;
    cudaGetSymbolAddress((void**)&xum,  g_xum);
    cudaGetSymbolAddress((void**)&h1m,  g_h1m);
    cudaGetSymbolAddress((void**)&s1,   g_s1);
    cudaGetSymbolAddress((void**)&s2,   g_s2);
    cudaGetSymbolAddress((void**)&s3,   g_s3);
    cudaGetSymbolAddress((void**)&d1,   g_d1);
    cudaGetSymbolAddress((void**)&d2,   g_d2);
    cudaGetSymbolAddress((void**)&wsq1, g_wsq1);
    cudaGetSymbolAddress((void**)&wsq2, g_wsq2);
    cudaGetSymbolAddress((void**)&wpk1, g_wpk1);
    cudaGetSymbolAddress((void**)&wpk2, g_wpk2);
    cudaGetSymbolAddress((void**)&wm3,  g_wm3);

    const int SMEM_DYN = 3 * (256 * 40 + 64 * 40) * 2;   // 76800 B -> 2 CTAs/SM
    cudaFuncSetAttribute(conv3x3_mma<512, true>,
                         cudaFuncAttributeMaxDynamicSharedMemorySize, SMEM_DYN);
    cudaFuncSetAttribute(conv3x3_mma<256, false>,
                         cudaFuncAttributeMaxDynamicSharedMemorySize, SMEM_DYN);

    // L1: styles (512 blocks) + wsq (768 blocks)
    prep1<<<1280, 256>>>(w, a1w, a1b, a2w, a2b, a3w, a3b, w1, w2, s1, s2, s3, wsq1, wsq2);
    // L2: demod (256 blocks) + prepack (6924 blocks)
    prep2<<<7180, 256>>>(s1, wsq1, s2, wsq2, w1, w2, w3, s3, d1, d2, wpk1, wpk2, wm3);
    // L3: upsample + modulate
    upmod_kernel<<<dim3(4, 128, 64), 256>>>(x, s1, xum);
    // L4 (ncu capture slot): conv1 512->256, persistent 296 CTAs
    conv3x3_mma<512, true><<<296, 256, SMEM_DYN>>>(xum, wpk1, b1, d1, s2,
                                                   h1m, (float*)nullptr);
    // L5: conv2 256->256 -> out_h (NCHW fp32)
    conv3x3_mma<256, false><<<296, 256, SMEM_DYN>>>(h1m, wpk2, b2, d2,
                                                    (const float*)nullptr,
                                                    (__half*)nullptr, out_h);
    // L6: rgb
    rgb_nchw<<<(B_ * HW * HW) / 256, 256>>>(out_h, wm3, b3, out_rgb);
}